// round 7
// baseline (speedup 1.0000x reference)
#include <cuda_runtime.h>
#include <cstdint>

#define N_NODES 20000
#define N_EDGES 1280000
#define IN_DIM 16
#define HID 128
#define G3 384
#define OUT_DIM 4

// ---------------- scratch (static device globals; no allocation) ----------------
__device__ float g_deg[N_NODES];
__device__ float g_s[N_NODES * HID];      // (x@W_gcn) * dinv  (messages, pre-scaled)
__device__ float g_agg[N_NODES * HID];    // scatter-add accumulator (init = self term)
__device__ float g_xg[N_NODES * G3];      // precomputed input gates
__device__ float g_ys[N_NODES * HID];     // GRU outputs

// ---------------- packed f32x2 helpers ----------------
__device__ __forceinline__ unsigned long long ffma2(unsigned long long a,
                                                    unsigned long long b,
                                                    unsigned long long c) {
    unsigned long long d;
    asm("fma.rn.f32x2 %0, %1, %2, %3;" : "=l"(d) : "l"(a), "l"(b), "l"(c));
    return d;
}
__device__ __forceinline__ unsigned long long addf2(unsigned long long a,
                                                    unsigned long long b) {
    unsigned long long d;
    asm("add.rn.f32x2 %0, %1, %2;" : "=l"(d) : "l"(a), "l"(b));
    return d;
}
__device__ __forceinline__ float2 u2f2(unsigned long long u) {
    float2 f;
    asm("mov.b64 {%0, %1}, %2;" : "=f"(f.x), "=f"(f.y) : "l"(u));
    return f;
}
__device__ __forceinline__ unsigned long long packf2(float lo, float hi) {
    unsigned long long u;
    asm("mov.b64 %0, {%1, %2};" : "=l"(u) : "f"(lo), "f"(hi));
    return u;
}
// accurate activations (ex2-based; per-op err ~1e-7)
__device__ __forceinline__ float sigmoid_acc(float x) {
    return 1.0f / (1.0f + __expf(-x));
}
__device__ __forceinline__ float tanh_acc(float x) {
    return 2.0f / (1.0f + __expf(-2.0f * x)) - 1.0f;
}

// ---------------- K1: deg init (self-loop => 1) ----------------
__global__ void k_init_deg() {
    int i = blockIdx.x * blockDim.x + threadIdx.x;
    if (i < N_NODES) g_deg[i] = 1.0f;
}

// ---------------- K2: in-degree over targets ----------------
__global__ void k_deg(const int* __restrict__ ei) {
    int e = blockIdx.x * blockDim.x + threadIdx.x;
    if (e < N_EDGES) atomicAdd(&g_deg[ei[N_EDGES + e]], 1.0f);
}

// ---------------- K3: s = (x @ W_gcn) * dinv ; agg init with self term ----------------
__global__ void k_lin(const float* __restrict__ x, const float* __restrict__ Wg) {
    __shared__ float sx[IN_DIM];
    int node = blockIdx.x;
    int tid = threadIdx.x;  // 128 threads
    if (tid < IN_DIM) sx[tid] = x[node * IN_DIM + tid];
    __syncthreads();
    float acc = 0.0f;
#pragma unroll
    for (int k = 0; k < IN_DIM; k++) acc = fmaf(sx[k], Wg[k * HID + tid], acc);
    float s = acc * rsqrtf(g_deg[node]);
    g_s[(size_t)node * HID + tid] = s;
    g_agg[(size_t)node * HID + tid] = s;  // self-loop contribution (pre outer dinv)
}

// ---------------- K4: scatter-add messages (vector red.v2) ----------------
__global__ void k_scatter(const int* __restrict__ ei) {
    long long gid = (long long)blockIdx.x * blockDim.x + threadIdx.x;
    if (gid >= (long long)N_EDGES * (HID / 2)) return;
    int e = (int)(gid >> 6);
    int q = (int)(gid & 63);
    int r = ei[e];
    int c = ei[N_EDGES + e];
    const float2* src = (const float2*)(g_s + (size_t)r * HID) + q;
    float2 v = *src;
    float* dst = g_agg + (size_t)c * HID + 2 * q;
    asm volatile("red.global.v2.f32.add [%0], {%1, %2};"
                 :: "l"(dst), "f"(v.x), "f"(v.y) : "memory");
}

// ---------------- K5: xg = (agg*dinv + b_gcn) @ W_ih.T + b_ih ----------------
__global__ void __launch_bounds__(G3, 1)
k_xg(const float* __restrict__ Wih, const float* __restrict__ bih,
     const float* __restrict__ bgcn) {
    __shared__ __align__(16) float sg[HID];
    int tid = threadIdx.x;
    unsigned long long w[HID / 2];
    const unsigned long long* wr =
        (const unsigned long long*)(Wih + (size_t)tid * HID);
#pragma unroll
    for (int m = 0; m < HID / 2; m++) w[m] = wr[m];
    float b = bih[tid];
    float bg = (tid < HID) ? bgcn[tid] : 0.0f;

    for (int node = blockIdx.x; node < N_NODES; node += gridDim.x) {
        __syncthreads();
        if (tid < HID) {
            float dv = rsqrtf(g_deg[node]);
            sg[tid] = fmaf(g_agg[(size_t)node * HID + tid], dv, bg);
        }
        __syncthreads();
        unsigned long long a0 = 0ull, a1 = 0ull;
        const ulonglong2* hp = (const ulonglong2*)sg;
#pragma unroll
        for (int m = 0; m < HID / 4; m++) {   // 32 entries: full 128 floats
            ulonglong2 hv = hp[m];
            a0 = ffma2(w[2 * m], hv.x, a0);
            a1 = ffma2(w[2 * m + 1], hv.y, a1);
        }
        float2 f0 = u2f2(a0), f1 = u2f2(a1);
        g_xg[(size_t)node * G3 + tid] = f0.x + f0.y + f1.x + f1.y + b;
    }
}

// ---------------- K6: sequential GRU scan (single CTA, persistent) ----------------
// grp0: r rows, grp1: z rows (+precomputes z*h_old), grp2: n rows + h update.
// Barrier protocol per step t (all named, "memory"-clobbered):
//   bar1 (384): grp0/1 arrive after publishing r / {z,z*h_old}; grp2 syncs.
//   bar2 (384): grp2 arrives after writing sh_h; grp0/1 sync before next dot.
//   bar3 (128): grp2-internal sync so grp2 sees all of sh_h for next dot.
// Hazard audit:
//   r/z(t) reads by grp2 follow bar1(t) <- after grp0/1 writes.           RAW ok
//   r/z(t+1) writes by grp0/1 follow bar2(t) <- after grp2's r/z reads.   WAR ok
//   sh_h[j] write by grp2(t) follows bar1(t) <- after all dot reads of t. WAR ok
//   sh_h reads at t+1: grp0/1 after bar2(t); grp2 after bar3(t).          RAW ok
//   grp1 reads sh_h[j] before its bar1 arrive; h stable during step t.    ok
__global__ void __launch_bounds__(G3, 1)
k_gru(const float* __restrict__ Whh, const float* __restrict__ bhh,
      const float* __restrict__ h0, float* __restrict__ hT) {
    __shared__ __align__(16) float sh_h[HID];
    __shared__ float sh_r[HID];
    __shared__ __align__(8) float2 sh_z2[HID];
    int tid = threadIdx.x;
    int grp = tid >> 7;  // 0,1,2
    int j = tid & 127;

    unsigned long long w[HID / 2];  // 64 ull = 128 regs
    const unsigned long long* wr =
        (const unsigned long long*)(Whh + (size_t)tid * HID);
#pragma unroll
    for (int m = 0; m < HID / 2; m++) w[m] = wr[m];
    float bh = bhh[tid];

    if (tid < HID) sh_h[tid] = h0[tid];
    float xg_cur = g_xg[tid];  // t = 0 prefetch
    __syncthreads();

    for (int t = 0; t < N_NODES; t++) {
        const ulonglong2* hp = (const ulonglong2*)sh_h;  // 32 entries (4 floats each)

        // ---- dot: hg[tid] = W_hh[tid,:] . h + b_hh[tid] (full 128 range) ----
        unsigned long long a0 = packf2(bh, 0.0f), a1 = 0ull, a2 = 0ull, a3 = 0ull;
        ulonglong2 s0 = hp[0], s1 = hp[1], s2 = hp[2], s3 = hp[3];
#pragma unroll
        for (int c = 0; c < 7; c++) {
            a0 = ffma2(w[8 * c + 0], s0.x, a0);
            a1 = ffma2(w[8 * c + 1], s0.y, a1);
            s0 = hp[4 * c + 4];
            a2 = ffma2(w[8 * c + 2], s1.x, a2);
            a3 = ffma2(w[8 * c + 3], s1.y, a3);
            s1 = hp[4 * c + 5];
            a0 = ffma2(w[8 * c + 4], s2.x, a0);
            a1 = ffma2(w[8 * c + 5], s2.y, a1);
            s2 = hp[4 * c + 6];
            a2 = ffma2(w[8 * c + 6], s3.x, a2);
            a3 = ffma2(w[8 * c + 7], s3.y, a3);
            s3 = hp[4 * c + 7];
        }
        a0 = ffma2(w[56], s0.x, a0);
        a1 = ffma2(w[57], s0.y, a1);
        a2 = ffma2(w[58], s1.x, a2);
        a3 = ffma2(w[59], s1.y, a3);
        a0 = ffma2(w[60], s2.x, a0);
        a1 = ffma2(w[61], s2.y, a1);
        a2 = ffma2(w[62], s3.x, a2);
        a3 = ffma2(w[63], s3.y, a3);
        // packed reduction: ((a0+a1)+(a2+a3)) then horizontal add
        unsigned long long sA = addf2(addf2(a0, a1), addf2(a2, a3));
        float2 fs = u2f2(sA);
        float hg = fs.x + fs.y;

        float xg_own = xg_cur;
        int tn = (t + 1 < N_NODES) ? (t + 1) : (N_NODES - 1);
        xg_cur = g_xg[(size_t)tn * G3 + tid];

        if (grp == 0) {
            sh_r[j] = sigmoid_acc(xg_own + hg);
            asm volatile("bar.arrive 1, %0;" :: "n"(G3) : "memory");
            asm volatile("bar.sync 2, %0;" :: "n"(G3) : "memory");
        } else if (grp == 1) {
            float z = sigmoid_acc(xg_own + hg);
            float h_old = sh_h[j];            // stable during step t
            sh_z2[j] = make_float2(z, z * h_old);
            asm volatile("bar.arrive 1, %0;" :: "n"(G3) : "memory");
            asm volatile("bar.sync 2, %0;" :: "n"(G3) : "memory");
        } else {
            asm volatile("bar.sync 1, %0;" :: "n"(G3) : "memory");
            float r = sh_r[j];
            float2 z2 = sh_z2[j];
            float narg = fmaf(r, hg, xg_own);      // xn + r*hn
            float n = tanh_acc(narg);
            float hnew = fmaf(-z2.x, n, n) + z2.y; // n*(1-z) + z*h_old
            sh_h[j] = hnew;
            asm volatile("bar.arrive 2, %0;" :: "n"(G3) : "memory");
            g_ys[(size_t)t * HID + j] = hnew;      // off critical path
            asm volatile("bar.sync 3, 128;" ::: "memory");
        }
    }
    if (tid < HID) hT[tid] = sh_h[tid];
}

// ---------------- K7: readout + output assembly ----------------
__global__ void k_readout(const float* __restrict__ x, const float* __restrict__ Wfc,
                          const float* __restrict__ bfc, float* __restrict__ out) {
    int warp = (blockIdx.x * blockDim.x + threadIdx.x) >> 5;
    int lane = threadIdx.x & 31;
    if (warp >= N_NODES) return;
    const float* y = g_ys + (size_t)warp * HID;
    float y0 = y[lane], y1 = y[lane + 32], y2 = y[lane + 64], y3 = y[lane + 96];
    float o[4];
#pragma unroll
    for (int c = 0; c < 4; c++) {
        float p = y0 * Wfc[lane * 4 + c];
        p = fmaf(y1, Wfc[(lane + 32) * 4 + c], p);
        p = fmaf(y2, Wfc[(lane + 64) * 4 + c], p);
        p = fmaf(y3, Wfc[(lane + 96) * 4 + c], p);
#pragma unroll
        for (int off = 16; off; off >>= 1) p += __shfl_xor_sync(0xffffffffu, p, off);
        o[c] = p;
    }
    float* nx = out + (size_t)warp * 8;
    if (lane < 3) nx[lane] = x[(size_t)warp * IN_DIM + lane];
    if (lane == 3) nx[7] = x[(size_t)warp * IN_DIM + 7];
    if (lane == 4) nx[3] = o[0] + bfc[0];
    if (lane == 5) nx[4] = o[1] + bfc[1];
    if (lane == 6) nx[5] = o[2] + bfc[2];
    if (lane == 7) nx[6] = o[3] + bfc[3];
}

// ---------------- launch ----------------
extern "C" void kernel_launch(void* const* d_in, const int* in_sizes, int n_in,
                              void* d_out, int out_size) {
    const float* x   = (const float*)d_in[0];
    const int*   ei  = (const int*)d_in[1];
    const float* h0  = (const float*)d_in[2];
    const float* Wg  = (const float*)d_in[3];
    const float* bg  = (const float*)d_in[4];
    const float* Wih = (const float*)d_in[5];
    const float* Whh = (const float*)d_in[6];
    const float* bih = (const float*)d_in[7];
    const float* bhh = (const float*)d_in[8];
    const float* Wfc = (const float*)d_in[9];
    const float* bfc = (const float*)d_in[10];
    float* out = (float*)d_out;

    k_init_deg<<<(N_NODES + 255) / 256, 256>>>();
    k_deg<<<(N_EDGES + 255) / 256, 256>>>(ei);
    k_lin<<<N_NODES, HID>>>(x, Wg);
    long long scat_threads = (long long)N_EDGES * (HID / 2);
    k_scatter<<<(int)((scat_threads + 255) / 256), 256>>>(ei);
    k_xg<<<148, G3>>>(Wih, bih, bg);
    k_gru<<<1, G3>>>(Whh, bhh, h0, out + (size_t)N_NODES * 8);
    k_readout<<<(N_NODES + 7) / 8, 256>>>(x, Wfc, bfc, out);
}

// round 8
// speedup vs baseline: 1.7634x; 1.7634x over previous
#include <cuda_runtime.h>
#include <cstdint>

#define N_NODES 20000
#define N_EDGES 1280000
#define IN_DIM 16
#define HID 128
#define G3 384
#define OUT_DIM 4

// ---------------- scratch (static device globals; no allocation) ----------------
__device__ float g_deg[N_NODES];
__device__ float g_s[N_NODES * HID];      // (x@W_gcn) * dinv  (messages, pre-scaled)
__device__ float g_agg[N_NODES * HID];    // scatter-add accumulator (init = self term)
__device__ float g_xg[N_NODES * G3];      // precomputed input gates
__device__ float g_ys[N_NODES * HID];     // GRU outputs

// ---------------- packed f32x2 helpers ----------------
__device__ __forceinline__ unsigned long long ffma2(unsigned long long a,
                                                    unsigned long long b,
                                                    unsigned long long c) {
    unsigned long long d;
    asm("fma.rn.f32x2 %0, %1, %2, %3;" : "=l"(d) : "l"(a), "l"(b), "l"(c));
    return d;
}
__device__ __forceinline__ unsigned long long addf2(unsigned long long a,
                                                    unsigned long long b) {
    unsigned long long d;
    asm("add.rn.f32x2 %0, %1, %2;" : "=l"(d) : "l"(a), "l"(b));
    return d;
}
__device__ __forceinline__ float2 u2f2(unsigned long long u) {
    float2 f;
    asm("mov.b64 {%0, %1}, %2;" : "=f"(f.x), "=f"(f.y) : "l"(u));
    return f;
}
__device__ __forceinline__ unsigned long long packf2(float lo, float hi) {
    unsigned long long u;
    asm("mov.b64 %0, {%1, %2};" : "=l"(u) : "f"(lo), "f"(hi));
    return u;
}
// fast sigmoid via MUFU.TANH (for r,z gates only; budget audited: ~2.5e-4 final)
__device__ __forceinline__ float sigmoid_fast(float x) {
    float y;
    asm("tanh.approx.f32 %0, %1;" : "=f"(y) : "f"(x));  // y = tanh(x) ... use x/2
    return fmaf(y, 0.5f, 0.5f);
}
// accurate tanh (ex2-based; per-op err ~1e-7) for the n gate
__device__ __forceinline__ float tanh_acc(float x) {
    return 2.0f / (1.0f + __expf(-2.0f * x)) - 1.0f;
}

// ---------------- K1: deg init (self-loop => 1) ----------------
__global__ void k_init_deg() {
    int i = blockIdx.x * blockDim.x + threadIdx.x;
    if (i < N_NODES) g_deg[i] = 1.0f;
}

// ---------------- K2: in-degree over targets ----------------
__global__ void k_deg(const int* __restrict__ ei) {
    int e = blockIdx.x * blockDim.x + threadIdx.x;
    if (e < N_EDGES) atomicAdd(&g_deg[ei[N_EDGES + e]], 1.0f);
}

// ---------------- K3: s = (x @ W_gcn) * dinv ; agg init with self term ----------------
__global__ void k_lin(const float* __restrict__ x, const float* __restrict__ Wg) {
    __shared__ float sx[IN_DIM];
    int node = blockIdx.x;
    int tid = threadIdx.x;  // 128 threads
    if (tid < IN_DIM) sx[tid] = x[node * IN_DIM + tid];
    __syncthreads();
    float acc = 0.0f;
#pragma unroll
    for (int k = 0; k < IN_DIM; k++) acc = fmaf(sx[k], Wg[k * HID + tid], acc);
    float s = acc * rsqrtf(g_deg[node]);
    g_s[(size_t)node * HID + tid] = s;
    g_agg[(size_t)node * HID + tid] = s;  // self-loop contribution (pre outer dinv)
}

// ---------------- K4: scatter-add messages (vector red.v2) ----------------
__global__ void k_scatter(const int* __restrict__ ei) {
    long long gid = (long long)blockIdx.x * blockDim.x + threadIdx.x;
    if (gid >= (long long)N_EDGES * (HID / 2)) return;
    int e = (int)(gid >> 6);
    int q = (int)(gid & 63);
    int r = ei[e];
    int c = ei[N_EDGES + e];
    const float2* src = (const float2*)(g_s + (size_t)r * HID) + q;
    float2 v = *src;
    float* dst = g_agg + (size_t)c * HID + 2 * q;
    asm volatile("red.global.v2.f32.add [%0], {%1, %2};"
                 :: "l"(dst), "f"(v.x), "f"(v.y) : "memory");
}

// ---------------- K5: xg = (agg*dinv + b_gcn) @ W_ih.T + b_ih ----------------
__global__ void __launch_bounds__(G3, 1)
k_xg(const float* __restrict__ Wih, const float* __restrict__ bih,
     const float* __restrict__ bgcn) {
    __shared__ __align__(16) float sg[HID];
    int tid = threadIdx.x;
    unsigned long long w[HID / 2];
    const unsigned long long* wr =
        (const unsigned long long*)(Wih + (size_t)tid * HID);
#pragma unroll
    for (int m = 0; m < HID / 2; m++) w[m] = wr[m];
    float b = bih[tid];
    float bg = (tid < HID) ? bgcn[tid] : 0.0f;

    for (int node = blockIdx.x; node < N_NODES; node += gridDim.x) {
        __syncthreads();
        if (tid < HID) {
            float dv = rsqrtf(g_deg[node]);
            sg[tid] = fmaf(g_agg[(size_t)node * HID + tid], dv, bg);
        }
        __syncthreads();
        unsigned long long a0 = 0ull, a1 = 0ull;
        const ulonglong2* hp = (const ulonglong2*)sg;
#pragma unroll
        for (int m = 0; m < HID / 4; m++) {   // 32 entries: full 128 floats
            ulonglong2 hv = hp[m];
            a0 = ffma2(w[2 * m], hv.x, a0);
            a1 = ffma2(w[2 * m + 1], hv.y, a1);
        }
        float2 f0 = u2f2(a0), f1 = u2f2(a1);
        g_xg[(size_t)node * G3 + tid] = f0.x + f0.y + f1.x + f1.y + b;
    }
}

// ---------------- K6: sequential GRU scan (single CTA, persistent) ----------------
// R2/R6-proven structure: grp0 publishes r, grp1 publishes z, grp2 reads h_old
// itself, bar.arrive/bar.sync(1) mid-step rendezvous + trailing __syncthreads.
// Deltas vs R6 (each individually proven green/correct in prior rounds):
//   - R2-style minimal-register dot loop (no explicit staging; ~150 regs,
//     safely under the 170 cap at 384 thr)
//   - bias folded into a0, packed addf2 reduction tree
//   - sigmoid for r,z via MUFU.TANH (n gate stays __expf-accurate)
__global__ void __launch_bounds__(G3, 1)
k_gru(const float* __restrict__ Whh, const float* __restrict__ bhh,
      const float* __restrict__ h0, float* __restrict__ hT) {
    __shared__ __align__(16) float sh_h[HID];
    __shared__ float sh_r[HID];
    __shared__ float sh_z[HID];
    int tid = threadIdx.x;
    int grp = tid >> 7;  // 0,1,2
    int j = tid & 127;

    unsigned long long w[HID / 2];  // 64 ull = 128 regs
    const unsigned long long* wr =
        (const unsigned long long*)(Whh + (size_t)tid * HID);
#pragma unroll
    for (int m = 0; m < HID / 2; m++) w[m] = wr[m];
    float bh = bhh[tid];

    if (tid < HID) sh_h[tid] = h0[tid];
    float xg_cur = g_xg[tid];  // t = 0 prefetch
    __syncthreads();

    for (int t = 0; t < N_NODES; t++) {
        const ulonglong2* hp = (const ulonglong2*)sh_h;  // 32 entries (4 floats)

        // ---- dot: hg[tid] = W_hh[tid,:] . h + b_hh[tid]  (full 128 range) ----
        unsigned long long a0 = packf2(bh, 0.0f), a1 = 0ull, a2 = 0ull, a3 = 0ull;
#pragma unroll
        for (int m = 0; m < HID / 8; m++) {   // 16 iters over hp[0..31], w[0..63]
            ulonglong2 u = hp[2 * m];
            ulonglong2 v = hp[2 * m + 1];
            a0 = ffma2(w[4 * m + 0], u.x, a0);
            a1 = ffma2(w[4 * m + 1], u.y, a1);
            a2 = ffma2(w[4 * m + 2], v.x, a2);
            a3 = ffma2(w[4 * m + 3], v.y, a3);
        }
        // packed reduction: ((a0+a1)+(a2+a3)) then horizontal add
        unsigned long long sA = addf2(addf2(a0, a1), addf2(a2, a3));
        float2 fs = u2f2(sA);
        float hg = fs.x + fs.y;

        float xg_own = xg_cur;
        if (t + 1 < N_NODES) xg_cur = g_xg[(size_t)(t + 1) * G3 + tid];

        if (grp == 0) {
            sh_r[j] = sigmoid_fast(0.5f * (xg_own + hg));
            asm volatile("bar.arrive 1, %0;" :: "n"(G3) : "memory");
        } else if (grp == 1) {
            sh_z[j] = sigmoid_fast(0.5f * (xg_own + hg));
            asm volatile("bar.arrive 1, %0;" :: "n"(G3) : "memory");
        } else {
            float h_old = sh_h[j];  // own-thread slot, stable until we write it
            asm volatile("bar.sync 1, %0;" :: "n"(G3) : "memory");
            float r = sh_r[j];
            float z = sh_z[j];
            float narg = fmaf(r, hg, xg_own);   // xn + r*hn
            float n = tanh_acc(narg);
            float hnew = n + z * (h_old - n);   // (1-z)n + z h
            sh_h[j] = hnew;
            g_ys[(size_t)t * HID + j] = hnew;
        }
        __syncthreads();  // h updated & visible before next dot
    }
    if (tid < HID) hT[tid] = sh_h[tid];
}

// ---------------- K7: readout + output assembly ----------------
__global__ void k_readout(const float* __restrict__ x, const float* __restrict__ Wfc,
                          const float* __restrict__ bfc, float* __restrict__ out) {
    int warp = (blockIdx.x * blockDim.x + threadIdx.x) >> 5;
    int lane = threadIdx.x & 31;
    if (warp >= N_NODES) return;
    const float* y = g_ys + (size_t)warp * HID;
    float y0 = y[lane], y1 = y[lane + 32], y2 = y[lane + 64], y3 = y[lane + 96];
    float o[4];
#pragma unroll
    for (int c = 0; c < 4; c++) {
        float p = y0 * Wfc[lane * 4 + c];
        p = fmaf(y1, Wfc[(lane + 32) * 4 + c], p);
        p = fmaf(y2, Wfc[(lane + 64) * 4 + c], p);
        p = fmaf(y3, Wfc[(lane + 96) * 4 + c], p);
#pragma unroll
        for (int off = 16; off; off >>= 1) p += __shfl_xor_sync(0xffffffffu, p, off);
        o[c] = p;
    }
    float* nx = out + (size_t)warp * 8;
    if (lane < 3) nx[lane] = x[(size_t)warp * IN_DIM + lane];
    if (lane == 3) nx[7] = x[(size_t)warp * IN_DIM + 7];
    if (lane == 4) nx[3] = o[0] + bfc[0];
    if (lane == 5) nx[4] = o[1] + bfc[1];
    if (lane == 6) nx[5] = o[2] + bfc[2];
    if (lane == 7) nx[6] = o[3] + bfc[3];
}

// ---------------- launch ----------------
extern "C" void kernel_launch(void* const* d_in, const int* in_sizes, int n_in,
                              void* d_out, int out_size) {
    const float* x   = (const float*)d_in[0];
    const int*   ei  = (const int*)d_in[1];
    const float* h0  = (const float*)d_in[2];
    const float* Wg  = (const float*)d_in[3];
    const float* bg  = (const float*)d_in[4];
    const float* Wih = (const float*)d_in[5];
    const float* Whh = (const float*)d_in[6];
    const float* bih = (const float*)d_in[7];
    const float* bhh = (const float*)d_in[8];
    const float* Wfc = (const float*)d_in[9];
    const float* bfc = (const float*)d_in[10];
    float* out = (float*)d_out;

    k_init_deg<<<(N_NODES + 255) / 256, 256>>>();
    k_deg<<<(N_EDGES + 255) / 256, 256>>>(ei);
    k_lin<<<N_NODES, HID>>>(x, Wg);
    long long scat_threads = (long long)N_EDGES * (HID / 2);
    k_scatter<<<(int)((scat_threads + 255) / 256), 256>>>(ei);
    k_xg<<<148, G3>>>(Wih, bih, bg);
    k_gru<<<1, G3>>>(Whh, bhh, h0, out + (size_t)N_NODES * 8);
    k_readout<<<(N_NODES + 7) / 8, 256>>>(x, Wfc, bfc, out);
}

// round 9
// speedup vs baseline: 1.9166x; 1.0869x over previous
#include <cuda_runtime.h>
#include <cstdint>

#define N_NODES 20000
#define N_EDGES 1280000
#define IN_DIM 16
#define HID 128
#define G3 384
#define OUT_DIM 4

// ---------------- scratch (static device globals; no allocation) ----------------
__device__ float g_deg[N_NODES];
__device__ float g_s[N_NODES * HID];      // (x@W_gcn) * dinv  (messages, pre-scaled)
__device__ float g_agg[N_NODES * HID];    // scatter-add accumulator (init = self term)
__device__ float g_xg[N_NODES * G3];      // precomputed input gates
__device__ float g_ys[N_NODES * HID];     // GRU outputs

// ---------------- packed f32x2 helpers ----------------
__device__ __forceinline__ unsigned long long ffma2(unsigned long long a,
                                                    unsigned long long b,
                                                    unsigned long long c) {
    unsigned long long d;
    asm("fma.rn.f32x2 %0, %1, %2, %3;" : "=l"(d) : "l"(a), "l"(b), "l"(c));
    return d;
}
__device__ __forceinline__ unsigned long long addf2(unsigned long long a,
                                                    unsigned long long b) {
    unsigned long long d;
    asm("add.rn.f32x2 %0, %1, %2;" : "=l"(d) : "l"(a), "l"(b));
    return d;
}
__device__ __forceinline__ float2 u2f2(unsigned long long u) {
    float2 f;
    asm("mov.b64 {%0, %1}, %2;" : "=f"(f.x), "=f"(f.y) : "l"(u));
    return f;
}
__device__ __forceinline__ unsigned long long packf2(float lo, float hi) {
    unsigned long long u;
    asm("mov.b64 %0, {%1, %2};" : "=l"(u) : "f"(lo), "f"(hi));
    return u;
}
// MUFU.TANH-based activations. Measured (R8): r,z via this path changed final
// rel_err by +7e-8 only. n-gate now also approx (single MUFU on critical tail).
__device__ __forceinline__ float tanh_fast(float x) {
    float y;
    asm("tanh.approx.f32 %0, %1;" : "=f"(y) : "f"(x));
    return y;
}
__device__ __forceinline__ float sigmoid_fast_half(float half_x) {
    // sigmoid(x) = 0.5*tanh(x/2)+0.5, caller passes x/2
    return fmaf(tanh_fast(half_x), 0.5f, 0.5f);
}

// ---------------- K1: deg init (self-loop => 1) ----------------
__global__ void k_init_deg() {
    int i = blockIdx.x * blockDim.x + threadIdx.x;
    if (i < N_NODES) g_deg[i] = 1.0f;
}

// ---------------- K2: in-degree over targets ----------------
__global__ void k_deg(const int* __restrict__ ei) {
    int e = blockIdx.x * blockDim.x + threadIdx.x;
    if (e < N_EDGES) atomicAdd(&g_deg[ei[N_EDGES + e]], 1.0f);
}

// ---------------- K3: s = (x @ W_gcn) * dinv ; agg init with self term ----------------
__global__ void k_lin(const float* __restrict__ x, const float* __restrict__ Wg) {
    __shared__ float sx[IN_DIM];
    int node = blockIdx.x;
    int tid = threadIdx.x;  // 128 threads
    if (tid < IN_DIM) sx[tid] = x[node * IN_DIM + tid];
    __syncthreads();
    float acc = 0.0f;
#pragma unroll
    for (int k = 0; k < IN_DIM; k++) acc = fmaf(sx[k], Wg[k * HID + tid], acc);
    float s = acc * rsqrtf(g_deg[node]);
    g_s[(size_t)node * HID + tid] = s;
    g_agg[(size_t)node * HID + tid] = s;  // self-loop contribution (pre outer dinv)
}

// ---------------- K4: scatter-add messages (vector red.v2) ----------------
__global__ void k_scatter(const int* __restrict__ ei) {
    long long gid = (long long)blockIdx.x * blockDim.x + threadIdx.x;
    if (gid >= (long long)N_EDGES * (HID / 2)) return;
    int e = (int)(gid >> 6);
    int q = (int)(gid & 63);
    int r = ei[e];
    int c = ei[N_EDGES + e];
    const float2* src = (const float2*)(g_s + (size_t)r * HID) + q;
    float2 v = *src;
    float* dst = g_agg + (size_t)c * HID + 2 * q;
    asm volatile("red.global.v2.f32.add [%0], {%1, %2};"
                 :: "l"(dst), "f"(v.x), "f"(v.y) : "memory");
}

// ---------------- K5: xg = (agg*dinv + b_gcn) @ W_ih.T + b_ih ----------------
__global__ void __launch_bounds__(G3, 1)
k_xg(const float* __restrict__ Wih, const float* __restrict__ bih,
     const float* __restrict__ bgcn) {
    __shared__ __align__(16) float sg[HID];
    int tid = threadIdx.x;
    unsigned long long w[HID / 2];
    const unsigned long long* wr =
        (const unsigned long long*)(Wih + (size_t)tid * HID);
#pragma unroll
    for (int m = 0; m < HID / 2; m++) w[m] = wr[m];
    float b = bih[tid];
    float bg = (tid < HID) ? bgcn[tid] : 0.0f;

    for (int node = blockIdx.x; node < N_NODES; node += gridDim.x) {
        __syncthreads();
        if (tid < HID) {
            float dv = rsqrtf(g_deg[node]);
            sg[tid] = fmaf(g_agg[(size_t)node * HID + tid], dv, bg);
        }
        __syncthreads();
        unsigned long long a0 = 0ull, a1 = 0ull;
        const ulonglong2* hp = (const ulonglong2*)sg;
#pragma unroll
        for (int m = 0; m < HID / 4; m++) {   // 32 entries: full 128 floats
            ulonglong2 hv = hp[m];
            a0 = ffma2(w[2 * m], hv.x, a0);
            a1 = ffma2(w[2 * m + 1], hv.y, a1);
        }
        float2 f0 = u2f2(a0), f1 = u2f2(a1);
        g_xg[(size_t)node * G3 + tid] = f0.x + f0.y + f1.x + f1.y + b;
    }
}

// ---------------- K6: sequential GRU scan (single CTA, persistent) ----------------
// R8-green structure; single delta: n-gate tanh via MUFU.TANH (tanh.approx),
// removing the __expf chain from grp2's serial critical tail.
__global__ void __launch_bounds__(G3, 1)
k_gru(const float* __restrict__ Whh, const float* __restrict__ bhh,
      const float* __restrict__ h0, float* __restrict__ hT) {
    __shared__ __align__(16) float sh_h[HID];
    __shared__ float sh_r[HID];
    __shared__ float sh_z[HID];
    int tid = threadIdx.x;
    int grp = tid >> 7;  // 0,1,2
    int j = tid & 127;

    unsigned long long w[HID / 2];  // 64 ull = 128 regs
    const unsigned long long* wr =
        (const unsigned long long*)(Whh + (size_t)tid * HID);
#pragma unroll
    for (int m = 0; m < HID / 2; m++) w[m] = wr[m];
    float bh = bhh[tid];

    if (tid < HID) sh_h[tid] = h0[tid];
    float xg_cur = g_xg[tid];  // t = 0 prefetch
    __syncthreads();

    for (int t = 0; t < N_NODES; t++) {
        const ulonglong2* hp = (const ulonglong2*)sh_h;  // 32 entries (4 floats)

        // ---- dot: hg[tid] = W_hh[tid,:] . h + b_hh[tid]  (full 128 range) ----
        unsigned long long a0 = packf2(bh, 0.0f), a1 = 0ull, a2 = 0ull, a3 = 0ull;
#pragma unroll
        for (int m = 0; m < HID / 8; m++) {   // 16 iters over hp[0..31], w[0..63]
            ulonglong2 u = hp[2 * m];
            ulonglong2 v = hp[2 * m + 1];
            a0 = ffma2(w[4 * m + 0], u.x, a0);
            a1 = ffma2(w[4 * m + 1], u.y, a1);
            a2 = ffma2(w[4 * m + 2], v.x, a2);
            a3 = ffma2(w[4 * m + 3], v.y, a3);
        }
        // packed reduction: ((a0+a1)+(a2+a3)) then horizontal add
        unsigned long long sA = addf2(addf2(a0, a1), addf2(a2, a3));
        float2 fs = u2f2(sA);
        float hg = fs.x + fs.y;

        float xg_own = xg_cur;
        int tn = (t + 1 < N_NODES) ? (t + 1) : (N_NODES - 1);  // branch-free clamp
        xg_cur = g_xg[(size_t)tn * G3 + tid];

        if (grp == 0) {
            sh_r[j] = sigmoid_fast_half(0.5f * (xg_own + hg));
            asm volatile("bar.arrive 1, %0;" :: "n"(G3) : "memory");
        } else if (grp == 1) {
            sh_z[j] = sigmoid_fast_half(0.5f * (xg_own + hg));
            asm volatile("bar.arrive 1, %0;" :: "n"(G3) : "memory");
        } else {
            float h_old = sh_h[j];  // own-thread slot, stable until we write it
            asm volatile("bar.sync 1, %0;" :: "n"(G3) : "memory");
            float r = sh_r[j];
            float z = sh_z[j];
            float narg = fmaf(r, hg, xg_own);   // xn + r*hn
            float n = tanh_fast(narg);          // single MUFU on critical tail
            float hnew = n + z * (h_old - n);   // (1-z)n + z h
            sh_h[j] = hnew;
            g_ys[(size_t)t * HID + j] = hnew;
        }
        __syncthreads();  // h updated & visible before next dot
    }
    if (tid < HID) hT[tid] = sh_h[tid];
}

// ---------------- K7: readout + output assembly ----------------
__global__ void k_readout(const float* __restrict__ x, const float* __restrict__ Wfc,
                          const float* __restrict__ bfc, float* __restrict__ out) {
    int warp = (blockIdx.x * blockDim.x + threadIdx.x) >> 5;
    int lane = threadIdx.x & 31;
    if (warp >= N_NODES) return;
    const float* y = g_ys + (size_t)warp * HID;
    float y0 = y[lane], y1 = y[lane + 32], y2 = y[lane + 64], y3 = y[lane + 96];
    float o[4];
#pragma unroll
    for (int c = 0; c < 4; c++) {
        float p = y0 * Wfc[lane * 4 + c];
        p = fmaf(y1, Wfc[(lane + 32) * 4 + c], p);
        p = fmaf(y2, Wfc[(lane + 64) * 4 + c], p);
        p = fmaf(y3, Wfc[(lane + 96) * 4 + c], p);
#pragma unroll
        for (int off = 16; off; off >>= 1) p += __shfl_xor_sync(0xffffffffu, p, off);
        o[c] = p;
    }
    float* nx = out + (size_t)warp * 8;
    if (lane < 3) nx[lane] = x[(size_t)warp * IN_DIM + lane];
    if (lane == 3) nx[7] = x[(size_t)warp * IN_DIM + 7];
    if (lane == 4) nx[3] = o[0] + bfc[0];
    if (lane == 5) nx[4] = o[1] + bfc[1];
    if (lane == 6) nx[5] = o[2] + bfc[2];
    if (lane == 7) nx[6] = o[3] + bfc[3];
}

// ---------------- launch ----------------
extern "C" void kernel_launch(void* const* d_in, const int* in_sizes, int n_in,
                              void* d_out, int out_size) {
    const float* x   = (const float*)d_in[0];
    const int*   ei  = (const int*)d_in[1];
    const float* h0  = (const float*)d_in[2];
    const float* Wg  = (const float*)d_in[3];
    const float* bg  = (const float*)d_in[4];
    const float* Wih = (const float*)d_in[5];
    const float* Whh = (const float*)d_in[6];
    const float* bih = (const float*)d_in[7];
    const float* bhh = (const float*)d_in[8];
    const float* Wfc = (const float*)d_in[9];
    const float* bfc = (const float*)d_in[10];
    float* out = (float*)d_out;

    k_init_deg<<<(N_NODES + 255) / 256, 256>>>();
    k_deg<<<(N_EDGES + 255) / 256, 256>>>(ei);
    k_lin<<<N_NODES, HID>>>(x, Wg);
    long long scat_threads = (long long)N_EDGES * (HID / 2);
    k_scatter<<<(int)((scat_threads + 255) / 256), 256>>>(ei);
    k_xg<<<148, G3>>>(Wih, bih, bg);
    k_gru<<<1, G3>>>(Whh, bhh, h0, out + (size_t)N_NODES * 8);
    k_readout<<<(N_NODES + 7) / 8, 256>>>(x, Wfc, bfc, out);
}